// round 13
// baseline (speedup 1.0000x reference)
#include <cuda_runtime.h>
#include <cstdint>

#define Bq 32
#define Tq 1024
#define Iq 64
#define Hq 512
#define Aq 16

#define OUT_N  (Bq*Tq*Aq)          // 524288
#define HN_N   (Bq*Hq)             // 16384
#define HN_OFF OUT_N
#define RNN_OFF (OUT_N + HN_N)     // 540672

#define CLU 8                      // CTAs per cluster
#define NCL 16                     // clusters (16*8 = 128 CTAs)
#define NB  2                      // batches per cluster
#define CHUNK_B 512                // bytes per source chunk (2 batches x 64 cols x 4B)
#define HSTRIDE (CLU*NB*64*4)      // bytes per h buffer (4096)
#define QT  256                    // timesteps per rnn launch (quarter)

typedef unsigned long long u64;

// ---- scratch (static device globals: allocation-free) ----
__device__ float g_xp[Tq*Bq*Hq];               // x_proj [t][b][j]   (64 MB)
__device__ float g_hidden[(size_t)Bq*Tq*Hq];   // fc1 output (64 MB)

// ---- streams/events for fork-join overlap (created at static init) ----
struct OverlapRes {
    cudaStream_t s2;
    cudaEvent_t  eq[3], ej;
    OverlapRes() {
        cudaStreamCreateWithFlags(&s2, cudaStreamNonBlocking);
        for (int i = 0; i < 3; i++) cudaEventCreateWithFlags(&eq[i], cudaEventDisableTiming);
        cudaEventCreateWithFlags(&ej, cudaEventDisableTiming);
    }
};
static OverlapRes g_ov;

// ================= helpers =================
__device__ __forceinline__ uint32_t smem_u32(const void* p) {
    uint32_t a;
    asm("{ .reg .u64 t; cvta.to.shared.u64 t, %1; cvt.u32.u64 %0, t; }" : "=r"(a) : "l"(p));
    return a;
}
__device__ __forceinline__ uint32_t mapa_u32(uint32_t laddr, uint32_t rank) {
    uint32_t r;
    asm("mapa.shared::cluster.u32 %0, %1, %2;" : "=r"(r) : "r"(laddr), "r"(rank));
    return r;
}
__device__ __forceinline__ void mbar_init(uint32_t mbar, uint32_t cnt) {
    asm volatile("mbarrier.init.shared.b64 [%0], %1;" :: "r"(mbar), "r"(cnt) : "memory");
}
__device__ __forceinline__ void mbar_arrive_expect_tx(uint32_t mbar, uint32_t tx) {
    asm volatile("mbarrier.arrive.expect_tx.shared.b64 _, [%0], %1;" :: "r"(mbar), "r"(tx) : "memory");
}
__device__ __forceinline__ void mbar_wait_parity(uint32_t mbar, uint32_t parity) {
    asm volatile(
        "{\n\t"
        ".reg .pred P1;\n\t"
        "WAIT_LOOP_%=:\n\t"
        "mbarrier.try_wait.parity.acquire.cta.shared::cta.b64 P1, [%0], %1, 0x989680;\n\t"
        "@P1 bra.uni WAIT_DONE_%=;\n\t"
        "bra.uni WAIT_LOOP_%=;\n\t"
        "WAIT_DONE_%=:\n\t"
        "}" :: "r"(mbar), "r"(parity) : "memory");
}
__device__ __forceinline__ void bulk_copy_to_peer(uint32_t dst_cluster, uint32_t src_cta,
                                                  uint32_t bytes, uint32_t rmbar_cluster) {
    asm volatile(
        "cp.async.bulk.shared::cluster.shared::cta.mbarrier::complete_tx::bytes [%0], [%1], %2, [%3];"
        :: "r"(dst_cluster), "r"(src_cta), "r"(bytes), "r"(rmbar_cluster) : "memory");
}
__device__ __forceinline__ void fence_proxy_async_cta() {
    asm volatile("fence.proxy.async.shared::cta;" ::: "memory");
}
__device__ __forceinline__ u64 ffma2(u64 a, u64 b, u64 c) {
    u64 d;
    asm("fma.rn.f32x2 %0, %1, %2, %3;" : "=l"(d) : "l"(a), "l"(b), "l"(c));
    return d;
}
__device__ __forceinline__ u64 packf2(float x, float y) {
    u64 r; asm("mov.b64 %0, {%1,%2};" : "=l"(r) : "f"(x), "f"(y)); return r;
}
__device__ __forceinline__ float2 unpackf2(u64 v) {
    float2 f; asm("mov.b64 {%0,%1}, %2;" : "=f"(f.x), "=f"(f.y) : "l"(v)); return f;
}
__device__ __forceinline__ uint32_t cvt_tf32(float f) {
    uint32_t r; asm("cvt.rna.tf32.f32 %0, %1;" : "=r"(r) : "f"(f)); return r;
}
__device__ __forceinline__ void ldsm_x4(uint32_t& d0, uint32_t& d1, uint32_t& d2, uint32_t& d3,
                                        uint32_t addr) {
    asm volatile("ldmatrix.sync.aligned.m8n8.x4.shared.b16 {%0,%1,%2,%3}, [%4];"
                 : "=r"(d0), "=r"(d1), "=r"(d2), "=r"(d3) : "r"(addr));
}
__device__ __forceinline__ void mma_tf32(float& c0, float& c1, float& c2, float& c3,
                                         uint32_t a0, uint32_t a1, uint32_t a2, uint32_t a3,
                                         uint32_t b0, uint32_t b1) {
    asm volatile("mma.sync.aligned.m16n8k8.row.col.f32.tf32.tf32.f32 "
                 "{%0,%1,%2,%3}, {%4,%5,%6,%7}, {%8,%9}, {%0,%1,%2,%3};"
                 : "+f"(c0), "+f"(c1), "+f"(c2), "+f"(c3)
                 : "r"(a0), "r"(a1), "r"(a2), "r"(a3), "r"(b0), "r"(b1));
}

// ---------------- profiling spacer (rnn(q0) -> launch slot 6 incl. 1 harness launch) ----------------
__global__ void nop_kernel() {}

// ---------------- x_proj ----------------
__global__ void xp_kernel(const float* __restrict__ inp, const float* __restrict__ w_ih) {
    const int b   = blockIdx.x;
    const int tc  = blockIdx.y;
    const int tid = threadIdx.x;  // 512
    __shared__ float s_in[32*64];
    const float* src = inp + (size_t)b*Tq*Iq + (size_t)tc*32*Iq;
    ((float4*)s_in)[tid] = ((const float4*)src)[tid];
    __syncthreads();

    float acc[32];
    #pragma unroll
    for (int tt = 0; tt < 32; tt++) acc[tt] = 0.f;
    #pragma unroll 8
    for (int i = 0; i < Iq; i++) {
        float w = w_ih[i*Hq + tid];
        #pragma unroll
        for (int tt = 0; tt < 32; tt++)
            acc[tt] = fmaf(s_in[tt*64 + i], w, acc[tt]);
    }
    #pragma unroll
    for (int tt = 0; tt < 32; tt++)
        g_xp[(size_t)(tc*32 + tt)*(Bq*Hq) + b*Hq + tid] = acc[tt];
}

// ---------------- RNN scan: pipelined step (psum double-buffer, per-warp push, 1 sync) ----
// Warps 0-3 finish step t (reduce/sigmoid/push) WHILE warps 4-7 already run GEMV(t+1).
// Each finisher warp pushes its contiguous 128B slice to all 8 CTAs (incl self) via
// cp.async.bulk; dest mbar (buf,src) accumulates 4x128B = 512B expect_tx.
// Stage-slot WAR guarded by cp.async.bulk.wait_group.read (source-side completion).
__global__ void __launch_bounds__(256, 1) __cluster_dims__(CLU, 1, 1)
rnn_kernel(const float* __restrict__ h_init, size_t h_stride, int t0, int tlen,
           const float* __restrict__ w_hh, float* __restrict__ outbuf) {
    __shared__ __align__(16) float  h_s[2][CLU][NB][64];   // 4KB [buf][src][b][col]
    __shared__ __align__(16) float  stage[2][128];         // 1KB outbound staging
    __shared__ __align__(16) float2 psum[2][NB][512];      // 16KB double-buffered
    __shared__ __align__(8)  unsigned long long mbar_s[2][CLU];

    const int tid = threadIdx.x;
    uint32_t rank;
    asm("mov.u32 %0, %%cluster_ctarank;" : "=r"(rank));
    const int cid = blockIdx.x >> 3;
    const int j0  = (int)rank * 64;
    const int s   = tid >> 5;               // k-segment == source chunk (one warp each)
    const int jl  = tid & 31;
    const int kb  = s * 64;

    u64 Wc0[32], Wc1[32];
    {
        const float* wbase = w_hh + (size_t)kb*Hq + j0 + jl*2;
        #pragma unroll
        for (int m = 0; m < 32; m++) {
            const float* wp = wbase + (size_t)(2*m)*Hq;
            Wc0[m] = packf2(wp[0], wp[Hq]);
            Wc1[m] = packf2(wp[1], wp[Hq + 1]);
        }
    }
    for (int e = tid; e < NB*Hq; e += 256) {
        int b = e >> 9, k = e & 511;
        h_s[0][k >> 6][b][k & 63] = h_init[(size_t)(cid*NB + b)*h_stride + k];
    }
    const uint32_t mbar0  = smem_u32(&mbar_s[0][0]);
    const uint32_t hbase  = smem_u32(&h_s[0][0][0][0]);
    const uint32_t sbase  = smem_u32(&stage[0][0]);
    if (tid == 0) {
        #pragma unroll
        for (int i = 0; i < 2*CLU; i++) mbar_init(mbar0 + 8u*i, 1);
    }
    __syncthreads();
    asm volatile("barrier.cluster.arrive.aligned;" ::: "memory");
    asm volatile("barrier.cluster.wait.aligned;"   ::: "memory");

    // finisher identity (warps 0-3): fb = s>>1, fc = (s&1)*32 + jl == tid&63
    const int fb = s >> 1;
    const int fc = ((s & 1) << 5) + jl;
    const float* xp_col = g_xp + (size_t)(cid*NB + fb)*Hq + j0 + fc;

    float xpv = 0.f;
    if (tid < 128) xpv = __ldcg(xp_col + (size_t)t0*(Bq*Hq));

    for (int t = 0; t < tlen; t++) {
        const int g   = t0 + t;
        const int cur = t & 1, nxt = cur ^ 1;
        // expects for step t+1 arrivals: ALL 8 sources (incl own rank; self-delivery by copy)
        if (t < tlen - 1 && tid < CLU)
            mbar_arrive_expect_tx(mbar0 + 8u*(nxt*CLU + tid), CHUNK_B);

        float xpn = 0.f;
        if (tid < 128 && t < tlen - 1)
            xpn = __ldcg(xp_col + (size_t)(g + 1)*(Bq*Hq));

        // wait for this warp's source chunk (self chunk also arrives via bulk copy)
        if (t > 0) {
            const uint32_t par = (uint32_t)(((t >> 1) - ((t & 1) ^ 1)) & 1);
            mbar_wait_parity(mbar0 + 8u*(cur*CLU + s), par);
        }

        // ---- GEMV: 2 batches x 2 cols; LDS.128 feeds two k-pairs per load ----
        const float* hb0 = &h_s[cur][s][0][0];
        const float* hb1 = &h_s[cur][s][1][0];
        u64 a00 = 0ull, a01 = 0ull, a10 = 0ull, a11 = 0ull;
        #pragma unroll
        for (int m = 0; m < 16; m++) {
            ulonglong2 h0 = *(const ulonglong2*)&hb0[4*m];   // broadcast LDS.128
            ulonglong2 h1 = *(const ulonglong2*)&hb1[4*m];
            a00 = ffma2(h0.x, Wc0[2*m],     a00);
            a01 = ffma2(h0.x, Wc1[2*m],     a01);
            a10 = ffma2(h1.x, Wc0[2*m],     a10);
            a11 = ffma2(h1.x, Wc1[2*m],     a11);
            a00 = ffma2(h0.y, Wc0[2*m + 1], a00);
            a01 = ffma2(h0.y, Wc1[2*m + 1], a01);
            a10 = ffma2(h1.y, Wc0[2*m + 1], a10);
            a11 = ffma2(h1.y, Wc1[2*m + 1], a11);
        }
        {
            float2 p00 = unpackf2(a00), p01 = unpackf2(a01);
            float2 p10 = unpackf2(a10), p11 = unpackf2(a11);
            *(float4*)&psum[cur][0][kb + jl*2] = make_float4(p00.x, p00.y, p01.x, p01.y);
            *(float4*)&psum[cur][1][kb + jl*2] = make_float4(p10.x, p10.y, p11.x, p11.y);
        }
        __syncthreads();   // the ONLY CTA-wide sync per step

        // ---- finisher warps 0-3: reduce, sigmoid, per-warp push; warps 4-7 race ahead ----
        if (tid < 128) {
            float2 acc = psum[cur][fb][fc];
            #pragma unroll
            for (int s2 = 1; s2 < 8; s2++) {
                float2 p = psum[cur][fb][s2*64 + fc];
                acc.x += p.x; acc.y += p.y;
            }
            float v  = acc.x + acc.y + xpv;
            float hv = 1.f / (1.f + __expf(-v));

            if (t < tlen - 1) {
                // WAR guard: the copy issued from stage[nxt] at step t-2 must be done reading
                if (jl == 0)
                    asm volatile("cp.async.bulk.wait_group.read 1;" ::: "memory");
                __syncwarp();
                stage[nxt][(s << 5) + jl] = hv;
                __syncwarp();
                if (jl == 0) {
                    fence_proxy_async_cta();
                    const uint32_t src  = sbase + (uint32_t)((nxt*128 + (s << 5)) * 4);
                    const uint32_t dloc = hbase + (uint32_t)(nxt*HSTRIDE
                                         + (int)rank*CHUNK_B + (s << 5)*4);
                    const uint32_t mloc = mbar0 + 8u*(uint32_t)(nxt*CLU + (int)rank);
                    #pragma unroll
                    for (int r = 0; r < CLU; r++)
                        bulk_copy_to_peer(mapa_u32(dloc, (uint32_t)r), src, 128,
                                          mapa_u32(mloc, (uint32_t)r));
                    asm volatile("cp.async.bulk.commit_group;" ::: "memory");
                }
            }
            // gmem stores off the critical path (after push)
            const size_t bglob = (size_t)(cid*NB + fb);
            outbuf[RNN_OFF + bglob*Tq*Hq + (size_t)g*Hq + j0 + fc] = hv;
            if (g == Tq - 1)
                outbuf[HN_OFF + bglob*Hq + j0 + fc] = hv;
        }
        xpv = xpn;
    }
}

// ---------------- fc1: tf32 mma.sync GEMM, QUARTER-aware (unchanged) ----------------
#define FM 128
#define FN 128
#define PAD 12
__global__ void __launch_bounds__(256, 1)
fc1_kernel(const float* __restrict__ A, const float* __restrict__ W,
           const float* __restrict__ bias, int qoff) {
    __shared__ __align__(16) uint32_t As[2][FM][PAD];
    __shared__ __align__(16) uint32_t Bs[2][FN][PAD];

    const int tid  = threadIdx.x;
    const int wid  = tid >> 5, lane = tid & 31;
    const int row0 = (blockIdx.y >> 1)*Tq + qoff + (blockIdx.y & 1)*FM;
    const int col0 = blockIdx.x * FN;
    const int wm   = wid >> 2;
    const int wn   = wid & 3;

    const int arow = tid >> 1, akq = (tid & 1) * 4;
    const int bk   = tid >> 5, bc  = (tid & 31) * 4;

    const uint32_t as0 = smem_u32(&As[0][0][0]);
    const uint32_t bs0 = smem_u32(&Bs[0][0][0]);
    const uint32_t a_off = ((uint32_t)((wm*64 + (lane & 15))*PAD + (lane >> 4)*4)) * 4u;
    const uint32_t b_off = ((uint32_t)((wn*32 + (lane & 7) + ((lane >> 4) & 1)*8)*PAD
                                       + ((lane >> 3) & 1)*4)) * 4u;
    const uint32_t BUFB = FM * PAD * 4u;

    float c[4][4][4];
    #pragma unroll
    for (int mt = 0; mt < 4; mt++)
        #pragma unroll
        for (int nt = 0; nt < 4; nt++)
            #pragma unroll
            for (int i = 0; i < 4; i++) c[mt][nt][i] = 0.f;

    uint4 ar; uint4 br;
    {
        float4 a4 = *(const float4*)&A[(size_t)(row0 + arow)*Hq + akq];
        float4 b4 = *(const float4*)&W[(size_t)bk*Hq + col0 + bc];
        ar = make_uint4(cvt_tf32(a4.x), cvt_tf32(a4.y), cvt_tf32(a4.z), cvt_tf32(a4.w));
        br = make_uint4(cvt_tf32(b4.x), cvt_tf32(b4.y), cvt_tf32(b4.z), cvt_tf32(b4.w));
    }

    for (int ks = 0; ks < 64; ks++) {
        const int buf = ks & 1;
        *(uint4*)&As[buf][arow][akq] = ar;
        Bs[buf][bc + 0][bk] = br.x;
        Bs[buf][bc + 1][bk] = br.y;
        Bs[buf][bc + 2][bk] = br.z;
        Bs[buf][bc + 3][bk] = br.w;
        if (ks < 63) {
            const int kt = (ks + 1) * 8;
            float4 a4 = *(const float4*)&A[(size_t)(row0 + arow)*Hq + kt + akq];
            float4 b4 = *(const float4*)&W[(size_t)(kt + bk)*Hq + col0 + bc];
            ar = make_uint4(cvt_tf32(a4.x), cvt_tf32(a4.y), cvt_tf32(a4.z), cvt_tf32(a4.w));
            br = make_uint4(cvt_tf32(b4.x), cvt_tf32(b4.y), cvt_tf32(b4.z), cvt_tf32(b4.w));
        }
        __syncthreads();

        uint32_t af[4][4], bf[4][2];
        #pragma unroll
        for (int mt = 0; mt < 4; mt++)
            ldsm_x4(af[mt][0], af[mt][1], af[mt][2], af[mt][3],
                    as0 + buf*BUFB + a_off + (uint32_t)(mt*16*PAD*4));
        #pragma unroll
        for (int np = 0; np < 2; np++)
            ldsm_x4(bf[2*np][0], bf[2*np][1], bf[2*np + 1][0], bf[2*np + 1][1],
                    bs0 + buf*BUFB + b_off + (uint32_t)(np*16*PAD*4));

        #pragma unroll
        for (int mt = 0; mt < 4; mt++)
            #pragma unroll
            for (int nt = 0; nt < 4; nt++)
                mma_tf32(c[mt][nt][0], c[mt][nt][1], c[mt][nt][2], c[mt][nt][3],
                         af[mt][0], af[mt][1], af[mt][2], af[mt][3],
                         bf[nt][0], bf[nt][1]);
    }

    const int gq = lane >> 2, tq = lane & 3;
    #pragma unroll
    for (int nt = 0; nt < 4; nt++) {
        const int cb = col0 + wn*32 + nt*8 + 2*tq;
        const float2 bv = *(const float2*)&bias[cb];
        #pragma unroll
        for (int mt = 0; mt < 4; mt++) {
            const int r0 = row0 + wm*64 + mt*16 + gq;
            float2 o0, o1;
            o0.x = fmaxf(c[mt][nt][0] + bv.x, 0.f);
            o0.y = fmaxf(c[mt][nt][1] + bv.y, 0.f);
            o1.x = fmaxf(c[mt][nt][2] + bv.x, 0.f);
            o1.y = fmaxf(c[mt][nt][3] + bv.y, 0.f);
            *(float2*)&g_hidden[(size_t)r0*Hq + cb]       = o0;
            *(float2*)&g_hidden[(size_t)(r0 + 8)*Hq + cb] = o1;
        }
    }
}

// ---------------- fc2 (quarter-aware, unchanged) ----------------
__global__ void fc2_kernel(const float* __restrict__ w2,
                           const float* __restrict__ b2,
                           float* __restrict__ out, int qoff) {
    __shared__ float w2s[Hq*Aq];
    const int tid = threadIdx.x;   // 256
    for (int e = tid; e < Hq*Aq; e += 256) w2s[e] = w2[e];
    __syncthreads();

    const int r = tid >> 4;
    const int a = tid & 15;
    const size_t row = (size_t)(blockIdx.x >> 4)*Tq + qoff + (blockIdx.x & 15)*16 + r;
    const float* hrow = &g_hidden[row*Hq];

    float acc = 0.f;
    #pragma unroll 8
    for (int k = 0; k < Hq; k += 4) {
        float4 hv = *(const float4*)&hrow[k];
        acc = fmaf(hv.x, w2s[(k+0)*Aq + a], acc);
        acc = fmaf(hv.y, w2s[(k+1)*Aq + a], acc);
        acc = fmaf(hv.z, w2s[(k+2)*Aq + a], acc);
        acc = fmaf(hv.w, w2s[(k+3)*Aq + a], acc);
    }
    float v = acc + b2[a];
    out[row*Aq + a] = 1.f / (1.f + __expf(-v));
}

extern "C" void kernel_launch(void* const* d_in, const int* in_sizes, int n_in,
                              void* d_out, int out_size) {
    const float* inp  = (const float*)d_in[0];
    const float* hn   = (const float*)d_in[1];
    const float* w_hh = (const float*)d_in[2];
    const float* w_ih = (const float*)d_in[3];
    const float* fc1w = (const float*)d_in[4];
    const float* fc1b = (const float*)d_in[5];
    const float* fc2w = (const float*)d_in[6];
    const float* fc2b = (const float*)d_in[7];
    float* out = (float*)d_out;

    xp_kernel<<<dim3(32, 32), 512>>>(inp, w_ih);                 // slot 2 (1 harness launch first)
    nop_kernel<<<1, 1>>>();                                      // 3
    nop_kernel<<<1, 1>>>();                                      // 4
    nop_kernel<<<1, 1>>>();                                      // 5

    rnn_kernel<<<NCL*CLU, 256>>>(hn, (size_t)Hq, 0, QT, w_hh, out);   // slot 6 <- ncu -s 5
    cudaEventRecord(g_ov.eq[0], 0);
    rnn_kernel<<<NCL*CLU, 256>>>(out + RNN_OFF + (size_t)(QT - 1)*Hq, (size_t)Tq*Hq, QT, QT, w_hh, out);
    cudaEventRecord(g_ov.eq[1], 0);
    rnn_kernel<<<NCL*CLU, 256>>>(out + RNN_OFF + (size_t)(2*QT - 1)*Hq, (size_t)Tq*Hq, 2*QT, QT, w_hh, out);
    cudaEventRecord(g_ov.eq[2], 0);
    rnn_kernel<<<NCL*CLU, 256>>>(out + RNN_OFF + (size_t)(3*QT - 1)*Hq, (size_t)Tq*Hq, 3*QT, QT, w_hh, out);

    for (int q = 0; q < 3; q++) {
        cudaStreamWaitEvent(g_ov.s2, g_ov.eq[q], 0);
        fc1_kernel<<<dim3(4, 64), 256, 0, g_ov.s2>>>(out + RNN_OFF, fc1w, fc1b, q*QT);
        fc2_kernel<<<512, 256, 0, g_ov.s2>>>(fc2w, fc2b, out, q*QT);
    }
    cudaEventRecord(g_ov.ej, g_ov.s2);

    fc1_kernel<<<dim3(4, 64), 256>>>(out + RNN_OFF, fc1w, fc1b, 3*QT);
    cudaStreamWaitEvent(0, g_ov.ej, 0);
    fc2_kernel<<<512, 256>>>(fc2w, fc2b, out, 3*QT);
}

// round 15
// speedup vs baseline: 1.1394x; 1.1394x over previous
#include <cuda_runtime.h>
#include <cstdint>

#define Bq 32
#define Tq 1024
#define Iq 64
#define Hq 512
#define Aq 16

#define OUT_N  (Bq*Tq*Aq)          // 524288
#define HN_N   (Bq*Hq)             // 16384
#define HN_OFF OUT_N
#define RNN_OFF (OUT_N + HN_N)     // 540672

#define CLU 8                      // CTAs per cluster
#define NCL 16                     // clusters (16*8 = 128 CTAs)
#define NB  2                      // batches per cluster
#define CHUNK_B 512                // bytes per source chunk
#define HSTRIDE (CLU*NB*64*4)      // bytes per h buffer (4096)
#define QT  256                    // timesteps per rnn launch (quarter)

typedef unsigned long long u64;

// ---- scratch (static device globals: allocation-free) ----
__device__ float g_xp[Tq*Bq*Hq];               // x_proj [t][b][j]   (64 MB)
__device__ float g_hidden[(size_t)Bq*Tq*Hq];   // fc1 output (64 MB)

// ---- streams/events for fork-join overlap (created at static init) ----
struct OverlapRes {
    cudaStream_t s2;
    cudaEvent_t  e0, eq[3], ej, ext;
    OverlapRes() {
        cudaStreamCreateWithFlags(&s2, cudaStreamNonBlocking);
        cudaEventCreateWithFlags(&e0, cudaEventDisableTiming);
        for (int i = 0; i < 3; i++) cudaEventCreateWithFlags(&eq[i], cudaEventDisableTiming);
        cudaEventCreateWithFlags(&ej, cudaEventDisableTiming);
        cudaEventCreateWithFlags(&ext, cudaEventDisableTiming);
    }
};
static OverlapRes g_ov;

// ================= helpers =================
__device__ __forceinline__ uint32_t smem_u32(const void* p) {
    uint32_t a;
    asm("{ .reg .u64 t; cvta.to.shared.u64 t, %1; cvt.u32.u64 %0, t; }" : "=r"(a) : "l"(p));
    return a;
}
__device__ __forceinline__ uint32_t mapa_u32(uint32_t laddr, uint32_t rank) {
    uint32_t r;
    asm("mapa.shared::cluster.u32 %0, %1, %2;" : "=r"(r) : "r"(laddr), "r"(rank));
    return r;
}
__device__ __forceinline__ void mbar_init(uint32_t mbar, uint32_t cnt) {
    asm volatile("mbarrier.init.shared.b64 [%0], %1;" :: "r"(mbar), "r"(cnt) : "memory");
}
__device__ __forceinline__ void mbar_arrive_expect_tx(uint32_t mbar, uint32_t tx) {
    asm volatile("mbarrier.arrive.expect_tx.shared.b64 _, [%0], %1;" :: "r"(mbar), "r"(tx) : "memory");
}
__device__ __forceinline__ void mbar_wait_parity(uint32_t mbar, uint32_t parity) {
    asm volatile(
        "{\n\t"
        ".reg .pred P1;\n\t"
        "WAIT_LOOP_%=:\n\t"
        "mbarrier.try_wait.parity.acquire.cta.shared::cta.b64 P1, [%0], %1, 0x989680;\n\t"
        "@P1 bra.uni WAIT_DONE_%=;\n\t"
        "bra.uni WAIT_LOOP_%=;\n\t"
        "WAIT_DONE_%=:\n\t"
        "}" :: "r"(mbar), "r"(parity) : "memory");
}
__device__ __forceinline__ void bulk_copy_to_peer(uint32_t dst_cluster, uint32_t src_cta,
                                                  uint32_t bytes, uint32_t rmbar_cluster) {
    asm volatile(
        "cp.async.bulk.shared::cluster.shared::cta.mbarrier::complete_tx::bytes [%0], [%1], %2, [%3];"
        :: "r"(dst_cluster), "r"(src_cta), "r"(bytes), "r"(rmbar_cluster) : "memory");
}
__device__ __forceinline__ void fence_proxy_async_cta() {
    asm volatile("fence.proxy.async.shared::cta;" ::: "memory");
}
__device__ __forceinline__ u64 ffma2(u64 a, u64 b, u64 c) {
    u64 d;
    asm("fma.rn.f32x2 %0, %1, %2, %3;" : "=l"(d) : "l"(a), "l"(b), "l"(c));
    return d;
}
__device__ __forceinline__ u64 packf2(float x, float y) {
    u64 r; asm("mov.b64 %0, {%1,%2};" : "=l"(r) : "f"(x), "f"(y)); return r;
}
__device__ __forceinline__ float2 unpackf2(u64 v) {
    float2 f; asm("mov.b64 {%0,%1}, %2;" : "=f"(f.x), "=f"(f.y) : "l"(v)); return f;
}
__device__ __forceinline__ uint32_t cvt_tf32(float f) {
    uint32_t r; asm("cvt.rna.tf32.f32 %0, %1;" : "=r"(r) : "f"(f)); return r;
}
__device__ __forceinline__ void ldsm_x4(uint32_t& d0, uint32_t& d1, uint32_t& d2, uint32_t& d3,
                                        uint32_t addr) {
    asm volatile("ldmatrix.sync.aligned.m8n8.x4.shared.b16 {%0,%1,%2,%3}, [%4];"
                 : "=r"(d0), "=r"(d1), "=r"(d2), "=r"(d3) : "r"(addr));
}
__device__ __forceinline__ void mma_tf32(float& c0, float& c1, float& c2, float& c3,
                                         uint32_t a0, uint32_t a1, uint32_t a2, uint32_t a3,
                                         uint32_t b0, uint32_t b1) {
    asm volatile("mma.sync.aligned.m16n8k8.row.col.f32.tf32.tf32.f32 "
                 "{%0,%1,%2,%3}, {%4,%5,%6,%7}, {%8,%9}, {%0,%1,%2,%3};"
                 : "+f"(c0), "+f"(c1), "+f"(c2), "+f"(c3)
                 : "r"(a0), "r"(a1), "r"(a2), "r"(a3), "r"(b0), "r"(b1));
}

// ---------------- x_proj (tc range [tc0, tc0+gridDim.y)) ----------------
__global__ void xp_kernel(const float* __restrict__ inp, const float* __restrict__ w_ih,
                          int tc0) {
    const int b   = blockIdx.x;
    const int tc  = tc0 + blockIdx.y;
    const int tid = threadIdx.x;  // 512
    __shared__ float s_in[32*64];
    const float* src = inp + (size_t)b*Tq*Iq + (size_t)tc*32*Iq;
    ((float4*)s_in)[tid] = ((const float4*)src)[tid];
    __syncthreads();

    float acc[32];
    #pragma unroll
    for (int tt = 0; tt < 32; tt++) acc[tt] = 0.f;
    #pragma unroll 8
    for (int i = 0; i < Iq; i++) {
        float w = w_ih[i*Hq + tid];
        #pragma unroll
        for (int tt = 0; tt < 32; tt++)
            acc[tt] = fmaf(s_in[tt*64 + i], w, acc[tt]);
    }
    #pragma unroll
    for (int tt = 0; tt < 32; tt++)
        g_xp[(size_t)(tc*32 + tt)*(Bq*Hq) + b*Hq + tid] = acc[tt];
}

// ---------------- RNN scan (quarter-range) — R12 structure, byte-for-byte ----------------
__global__ void __launch_bounds__(256, 1) __cluster_dims__(CLU, 1, 1)
rnn_kernel(const float* __restrict__ h_init, size_t h_stride, int t0, int tlen,
           const float* __restrict__ w_hh, float* __restrict__ outbuf) {
    __shared__ __align__(16) float  h_s[2][CLU][NB][64];
    __shared__ __align__(16) float  stage[2][NB*64];
    __shared__ __align__(16) float2 psum[NB][512];
    __shared__ __align__(8)  unsigned long long mbar_s[2][CLU];

    const int tid = threadIdx.x;
    uint32_t rank;
    asm("mov.u32 %0, %%cluster_ctarank;" : "=r"(rank));
    const int cid = blockIdx.x >> 3;
    const int j0  = (int)rank * 64;
    const int s   = tid >> 5;
    const int jl  = tid & 31;
    const int kb  = s * 64;

    u64 Wc0[32], Wc1[32];
    {
        const float* wbase = w_hh + (size_t)kb*Hq + j0 + jl*2;
        #pragma unroll
        for (int m = 0; m < 32; m++) {
            const float* wp = wbase + (size_t)(2*m)*Hq;
            Wc0[m] = packf2(wp[0], wp[Hq]);
            Wc1[m] = packf2(wp[1], wp[Hq + 1]);
        }
    }
    for (int e = tid; e < NB*Hq; e += 256) {
        int b = e >> 9, k = e & 511;
        h_s[0][k >> 6][b][k & 63] = h_init[(size_t)(cid*NB + b)*h_stride + k];
    }
    const uint32_t mbar0  = smem_u32(&mbar_s[0][0]);
    const uint32_t hbase  = smem_u32(&h_s[0][0][0][0]);
    const uint32_t sbase  = smem_u32(&stage[0][0]);
    if (tid == 0) {
        #pragma unroll
        for (int i = 0; i < 2*CLU; i++) mbar_init(mbar0 + 8u*i, 1);
    }
    __syncthreads();
    asm volatile("barrier.cluster.arrive.aligned;" ::: "memory");
    asm volatile("barrier.cluster.wait.aligned;"   ::: "memory");

    const int fb = tid >> 6;
    const int fc = tid & 63;
    uint32_t dst_p = 0, mb_p = 0;
    if (tid < CLU) {
        dst_p = mapa_u32(hbase + (uint32_t)rank * CHUNK_B, (uint32_t)tid);
        mb_p  = mapa_u32(mbar0 + 8u*rank, (uint32_t)tid);
    }
    const bool is_pusher = (tid < CLU) && (tid != (int)rank);
    const float* xp_col = g_xp + (size_t)(cid*NB + fb)*Hq + j0 + fc;

    float xpv = 0.f;
    if (tid < 128) xpv = __ldcg(xp_col + (size_t)t0*(Bq*Hq));

    for (int t = 0; t < tlen; t++) {
        const int g   = t0 + t;
        const int cur = t & 1, nxt = cur ^ 1;
        if (t < tlen - 1 && tid < CLU && tid != (int)rank)
            mbar_arrive_expect_tx(mbar0 + 8u*(nxt*CLU + tid), CHUNK_B);

        float xpn = 0.f;
        if (tid < 128 && t < tlen - 1)
            xpn = __ldcg(xp_col + (size_t)(g + 1)*(Bq*Hq));

        if (t > 0 && s != (int)rank) {
            const uint32_t par = (uint32_t)(((t >> 1) - ((t & 1) ^ 1)) & 1);
            mbar_wait_parity(mbar0 + 8u*(cur*CLU + s), par);
        }

        // ---- GEMV: 2 batches x 2 cols; LDS.128 feeds two k-pairs per load ----
        const float* hb0 = &h_s[cur][s][0][0];
        const float* hb1 = &h_s[cur][s][1][0];
        u64 a00 = 0ull, a01 = 0ull, a10 = 0ull, a11 = 0ull;
        #pragma unroll
        for (int m = 0; m < 16; m++) {
            ulonglong2 h0 = *(const ulonglong2*)&hb0[4*m];   // broadcast LDS.128
            ulonglong2 h1 = *(const ulonglong2*)&hb1[4*m];
            a00 = ffma2(h0.x, Wc0[2*m],     a00);
            a01 = ffma2(h0.x, Wc1[2*m],     a01);
            a10 = ffma2(h1.x, Wc0[2*m],     a10);
            a11 = ffma2(h1.x, Wc1[2*m],     a11);
            a00 = ffma2(h0.y, Wc0[2*m + 1], a00);
            a01 = ffma2(h0.y, Wc1[2*m + 1], a01);
            a10 = ffma2(h1.y, Wc0[2*m + 1], a10);
            a11 = ffma2(h1.y, Wc1[2*m + 1], a11);
        }
        {
            float2 p00 = unpackf2(a00), p01 = unpackf2(a01);
            float2 p10 = unpackf2(a10), p11 = unpackf2(a11);
            *(float4*)&psum[0][kb + jl*2] = make_float4(p00.x, p00.y, p01.x, p01.y);
            *(float4*)&psum[1][kb + jl*2] = make_float4(p10.x, p10.y, p11.x, p11.y);
        }
        __syncthreads();

        if (tid < 128) {
            float2 acc = psum[fb][fc];
            #pragma unroll
            for (int s2 = 1; s2 < 8; s2++) {
                float2 p = psum[fb][s2*64 + fc];
                acc.x += p.x; acc.y += p.y;
            }
            float v  = acc.x + acc.y + xpv;
            float hv = 1.f / (1.f + __expf(-v));
            const size_t bglob = (size_t)(cid*NB + fb);
            outbuf[RNN_OFF + bglob*Tq*Hq + (size_t)g*Hq + j0 + fc] = hv;
            if (g == Tq - 1) {
                outbuf[HN_OFF + bglob*Hq + j0 + fc] = hv;
            } else if (t < tlen - 1) {
                stage[nxt][fb*64 + fc] = hv;
                h_s[nxt][rank][fb][fc] = hv;
            }
        }
        xpv = xpn;
        __syncthreads();

        if (t < tlen - 1 && is_pusher) {
            fence_proxy_async_cta();
            bulk_copy_to_peer(dst_p + (uint32_t)(nxt * HSTRIDE),
                              sbase + (uint32_t)(nxt * CHUNK_B),
                              CHUNK_B,
                              mb_p + (uint32_t)(nxt * (CLU*8)));
        }
    }
}

// ---------------- fc1: tf32 mma.sync GEMM, QUARTER-aware (unchanged) ----------------
#define FM 128
#define FN 128
#define PAD 12
__global__ void __launch_bounds__(256, 1)
fc1_kernel(const float* __restrict__ A, const float* __restrict__ W,
           const float* __restrict__ bias, int qoff) {
    __shared__ __align__(16) uint32_t As[2][FM][PAD];
    __shared__ __align__(16) uint32_t Bs[2][FN][PAD];

    const int tid  = threadIdx.x;
    const int wid  = tid >> 5, lane = tid & 31;
    const int row0 = (blockIdx.y >> 1)*Tq + qoff + (blockIdx.y & 1)*FM;
    const int col0 = blockIdx.x * FN;
    const int wm   = wid >> 2;
    const int wn   = wid & 3;

    const int arow = tid >> 1, akq = (tid & 1) * 4;
    const int bk   = tid >> 5, bc  = (tid & 31) * 4;

    const uint32_t as0 = smem_u32(&As[0][0][0]);
    const uint32_t bs0 = smem_u32(&Bs[0][0][0]);
    const uint32_t a_off = ((uint32_t)((wm*64 + (lane & 15))*PAD + (lane >> 4)*4)) * 4u;
    const uint32_t b_off = ((uint32_t)((wn*32 + (lane & 7) + ((lane >> 4) & 1)*8)*PAD
                                       + ((lane >> 3) & 1)*4)) * 4u;
    const uint32_t BUFB = FM * PAD * 4u;

    float c[4][4][4];
    #pragma unroll
    for (int mt = 0; mt < 4; mt++)
        #pragma unroll
        for (int nt = 0; nt < 4; nt++)
            #pragma unroll
            for (int i = 0; i < 4; i++) c[mt][nt][i] = 0.f;

    uint4 ar; uint4 br;
    {
        float4 a4 = *(const float4*)&A[(size_t)(row0 + arow)*Hq + akq];
        float4 b4 = *(const float4*)&W[(size_t)bk*Hq + col0 + bc];
        ar = make_uint4(cvt_tf32(a4.x), cvt_tf32(a4.y), cvt_tf32(a4.z), cvt_tf32(a4.w));
        br = make_uint4(cvt_tf32(b4.x), cvt_tf32(b4.y), cvt_tf32(b4.z), cvt_tf32(b4.w));
    }

    for (int ks = 0; ks < 64; ks++) {
        const int buf = ks & 1;
        *(uint4*)&As[buf][arow][akq] = ar;
        Bs[buf][bc + 0][bk] = br.x;
        Bs[buf][bc + 1][bk] = br.y;
        Bs[buf][bc + 2][bk] = br.z;
        Bs[buf][bc + 3][bk] = br.w;
        if (ks < 63) {
            const int kt = (ks + 1) * 8;
            float4 a4 = *(const float4*)&A[(size_t)(row0 + arow)*Hq + kt + akq];
            float4 b4 = *(const float4*)&W[(size_t)(kt + bk)*Hq + col0 + bc];
            ar = make_uint4(cvt_tf32(a4.x), cvt_tf32(a4.y), cvt_tf32(a4.z), cvt_tf32(a4.w));
            br = make_uint4(cvt_tf32(b4.x), cvt_tf32(b4.y), cvt_tf32(b4.z), cvt_tf32(b4.w));
        }
        __syncthreads();

        uint32_t af[4][4], bf[4][2];
        #pragma unroll
        for (int mt = 0; mt < 4; mt++)
            ldsm_x4(af[mt][0], af[mt][1], af[mt][2], af[mt][3],
                    as0 + buf*BUFB + a_off + (uint32_t)(mt*16*PAD*4));
        #pragma unroll
        for (int np = 0; np < 2; np++)
            ldsm_x4(bf[2*np][0], bf[2*np][1], bf[2*np + 1][0], bf[2*np + 1][1],
                    bs0 + buf*BUFB + b_off + (uint32_t)(np*16*PAD*4));

        #pragma unroll
        for (int mt = 0; mt < 4; mt++)
            #pragma unroll
            for (int nt = 0; nt < 4; nt++)
                mma_tf32(c[mt][nt][0], c[mt][nt][1], c[mt][nt][2], c[mt][nt][3],
                         af[mt][0], af[mt][1], af[mt][2], af[mt][3],
                         bf[nt][0], bf[nt][1]);
    }

    const int gq = lane >> 2, tq = lane & 3;
    #pragma unroll
    for (int nt = 0; nt < 4; nt++) {
        const int cb = col0 + wn*32 + nt*8 + 2*tq;
        const float2 bv = *(const float2*)&bias[cb];
        #pragma unroll
        for (int mt = 0; mt < 4; mt++) {
            const int r0 = row0 + wm*64 + mt*16 + gq;
            float2 o0, o1;
            o0.x = fmaxf(c[mt][nt][0] + bv.x, 0.f);
            o0.y = fmaxf(c[mt][nt][1] + bv.y, 0.f);
            o1.x = fmaxf(c[mt][nt][2] + bv.x, 0.f);
            o1.y = fmaxf(c[mt][nt][3] + bv.y, 0.f);
            *(float2*)&g_hidden[(size_t)r0*Hq + cb]       = o0;
            *(float2*)&g_hidden[(size_t)(r0 + 8)*Hq + cb] = o1;
        }
    }
}

// ---------------- fc2 (quarter-aware, unchanged) ----------------
__global__ void fc2_kernel(const float* __restrict__ w2,
                           const float* __restrict__ b2,
                           float* __restrict__ out, int qoff) {
    __shared__ float w2s[Hq*Aq];
    const int tid = threadIdx.x;   // 256
    for (int e = tid; e < Hq*Aq; e += 256) w2s[e] = w2[e];
    __syncthreads();

    const int r = tid >> 4;
    const int a = tid & 15;
    const size_t row = (size_t)(blockIdx.x >> 4)*Tq + qoff + (blockIdx.x & 15)*16 + r;
    const float* hrow = &g_hidden[row*Hq];

    float acc = 0.f;
    #pragma unroll 8
    for (int k = 0; k < Hq; k += 4) {
        float4 hv = *(const float4*)&hrow[k];
        acc = fmaf(hv.x, w2s[(k+0)*Aq + a], acc);
        acc = fmaf(hv.y, w2s[(k+1)*Aq + a], acc);
        acc = fmaf(hv.z, w2s[(k+2)*Aq + a], acc);
        acc = fmaf(hv.w, w2s[(k+3)*Aq + a], acc);
    }
    float v = acc + b2[a];
    out[row*Aq + a] = 1.f / (1.f + __expf(-v));
}

extern "C" void kernel_launch(void* const* d_in, const int* in_sizes, int n_in,
                              void* d_out, int out_size) {
    const float* inp  = (const float*)d_in[0];
    const float* hn   = (const float*)d_in[1];
    const float* w_hh = (const float*)d_in[2];
    const float* w_ih = (const float*)d_in[3];
    const float* fc1w = (const float*)d_in[4];
    const float* fc1b = (const float*)d_in[5];
    const float* fc2w = (const float*)d_in[6];
    const float* fc2b = (const float*)d_in[7];
    float* out = (float*)d_out;

    // capture-legal fork: s2 joins the graph via an event recorded on the origin stream
    cudaEventRecord(g_ov.e0, 0);
    xp_kernel<<<dim3(32, 8), 512>>>(inp, w_ih, 0);                      // xp head (t<256)
    cudaStreamWaitEvent(g_ov.s2, g_ov.e0, 0);                           // s2 enters capture
    xp_kernel<<<dim3(32, 24), 512, 0, g_ov.s2>>>(inp, w_ih, 8);         // xp tail overlaps rnn q0
    cudaEventRecord(g_ov.ext, g_ov.s2);

    rnn_kernel<<<NCL*CLU, 256>>>(hn, (size_t)Hq, 0, QT, w_hh, out);
    cudaEventRecord(g_ov.eq[0], 0);

    cudaStreamWaitEvent(0, g_ov.ext, 0);   // rnn q1 needs xp[256:512)
    rnn_kernel<<<NCL*CLU, 256>>>(out + RNN_OFF + (size_t)(QT - 1)*Hq, (size_t)Tq*Hq, QT, QT, w_hh, out);
    cudaEventRecord(g_ov.eq[1], 0);
    rnn_kernel<<<NCL*CLU, 256>>>(out + RNN_OFF + (size_t)(2*QT - 1)*Hq, (size_t)Tq*Hq, 2*QT, QT, w_hh, out);
    cudaEventRecord(g_ov.eq[2], 0);
    rnn_kernel<<<NCL*CLU, 256>>>(out + RNN_OFF + (size_t)(3*QT - 1)*Hq, (size_t)Tq*Hq, 3*QT, QT, w_hh, out);

    for (int q = 0; q < 3; q++) {
        cudaStreamWaitEvent(g_ov.s2, g_ov.eq[q], 0);
        fc1_kernel<<<dim3(4, 64), 256, 0, g_ov.s2>>>(out + RNN_OFF, fc1w, fc1b, q*QT);
        fc2_kernel<<<512, 256, 0, g_ov.s2>>>(fc2w, fc2b, out, q*QT);
    }
    cudaEventRecord(g_ov.ej, g_ov.s2);

    fc1_kernel<<<dim3(4, 64), 256>>>(out + RNN_OFF, fc1w, fc1b, 3*QT);
    cudaStreamWaitEvent(0, g_ov.ej, 0);
    fc2_kernel<<<512, 256>>>(fc2w, fc2b, out, 3*QT);
}

// round 16
// speedup vs baseline: 1.1693x; 1.0263x over previous
#include <cuda_runtime.h>
#include <cstdint>

#define Bq 32
#define Tq 1024
#define Iq 64
#define Hq 512
#define Aq 16

#define OUT_N  (Bq*Tq*Aq)          // 524288
#define HN_N   (Bq*Hq)             // 16384
#define HN_OFF OUT_N
#define RNN_OFF (OUT_N + HN_N)     // 540672

#define CLU 8                      // CTAs per cluster
#define NCL 16                     // clusters (16*8 = 128 CTAs)
#define NB  2                      // batches per cluster
#define CHUNK_B 512                // bytes per source chunk
#define HSTRIDE (CLU*NB*64*4)      // bytes per h buffer (4096)
#define QT  256                    // timesteps per rnn launch (quarter)

typedef unsigned long long u64;

// ---- scratch (static device globals: allocation-free) ----
__device__ float g_xp[Tq*Bq*Hq];               // x_proj [t][b][j]   (64 MB)
__device__ float g_hidden[(size_t)Bq*Tq*Hq];   // fc1 output (64 MB)

// ---- streams/events for fork-join overlap (created at static init) ----
struct OverlapRes {
    cudaStream_t s2;
    cudaEvent_t  eq[3], ej;
    OverlapRes() {
        cudaStreamCreateWithFlags(&s2, cudaStreamNonBlocking);
        for (int i = 0; i < 3; i++) cudaEventCreateWithFlags(&eq[i], cudaEventDisableTiming);
        cudaEventCreateWithFlags(&ej, cudaEventDisableTiming);
    }
};
static OverlapRes g_ov;

// ================= helpers =================
__device__ __forceinline__ uint32_t smem_u32(const void* p) {
    uint32_t a;
    asm("{ .reg .u64 t; cvta.to.shared.u64 t, %1; cvt.u32.u64 %0, t; }" : "=r"(a) : "l"(p));
    return a;
}
__device__ __forceinline__ uint32_t mapa_u32(uint32_t laddr, uint32_t rank) {
    uint32_t r;
    asm("mapa.shared::cluster.u32 %0, %1, %2;" : "=r"(r) : "r"(laddr), "r"(rank));
    return r;
}
__device__ __forceinline__ void mbar_init(uint32_t mbar, uint32_t cnt) {
    asm volatile("mbarrier.init.shared.b64 [%0], %1;" :: "r"(mbar), "r"(cnt) : "memory");
}
__device__ __forceinline__ void mbar_arrive_expect_tx(uint32_t mbar, uint32_t tx) {
    asm volatile("mbarrier.arrive.expect_tx.shared.b64 _, [%0], %1;" :: "r"(mbar), "r"(tx) : "memory");
}
__device__ __forceinline__ void mbar_wait_parity(uint32_t mbar, uint32_t parity) {
    asm volatile(
        "{\n\t"
        ".reg .pred P1;\n\t"
        "WAIT_LOOP_%=:\n\t"
        "mbarrier.try_wait.parity.acquire.cta.shared::cta.b64 P1, [%0], %1, 0x989680;\n\t"
        "@P1 bra.uni WAIT_DONE_%=;\n\t"
        "bra.uni WAIT_LOOP_%=;\n\t"
        "WAIT_DONE_%=:\n\t"
        "}" :: "r"(mbar), "r"(parity) : "memory");
}
__device__ __forceinline__ void bulk_copy_to_peer(uint32_t dst_cluster, uint32_t src_cta,
                                                  uint32_t bytes, uint32_t rmbar_cluster) {
    asm volatile(
        "cp.async.bulk.shared::cluster.shared::cta.mbarrier::complete_tx::bytes [%0], [%1], %2, [%3];"
        :: "r"(dst_cluster), "r"(src_cta), "r"(bytes), "r"(rmbar_cluster) : "memory");
}
__device__ __forceinline__ void fence_proxy_async_cta() {
    asm volatile("fence.proxy.async.shared::cta;" ::: "memory");
}
__device__ __forceinline__ u64 ffma2(u64 a, u64 b, u64 c) {
    u64 d;
    asm("fma.rn.f32x2 %0, %1, %2, %3;" : "=l"(d) : "l"(a), "l"(b), "l"(c));
    return d;
}
__device__ __forceinline__ u64 packf2(float x, float y) {
    u64 r; asm("mov.b64 %0, {%1,%2};" : "=l"(r) : "f"(x), "f"(y)); return r;
}
__device__ __forceinline__ float2 unpackf2(u64 v) {
    float2 f; asm("mov.b64 {%0,%1}, %2;" : "=f"(f.x), "=f"(f.y) : "l"(v)); return f;
}
__device__ __forceinline__ float hsum2(u64 v) { float2 f = unpackf2(v); return f.x + f.y; }
__device__ __forceinline__ uint32_t cvt_tf32(float f) {
    uint32_t r; asm("cvt.rna.tf32.f32 %0, %1;" : "=r"(r) : "f"(f)); return r;
}
__device__ __forceinline__ void ldsm_x4(uint32_t& d0, uint32_t& d1, uint32_t& d2, uint32_t& d3,
                                        uint32_t addr) {
    asm volatile("ldmatrix.sync.aligned.m8n8.x4.shared.b16 {%0,%1,%2,%3}, [%4];"
                 : "=r"(d0), "=r"(d1), "=r"(d2), "=r"(d3) : "r"(addr));
}
__device__ __forceinline__ void mma_tf32(float& c0, float& c1, float& c2, float& c3,
                                         uint32_t a0, uint32_t a1, uint32_t a2, uint32_t a3,
                                         uint32_t b0, uint32_t b1) {
    asm volatile("mma.sync.aligned.m16n8k8.row.col.f32.tf32.tf32.f32 "
                 "{%0,%1,%2,%3}, {%4,%5,%6,%7}, {%8,%9}, {%0,%1,%2,%3};"
                 : "+f"(c0), "+f"(c1), "+f"(c2), "+f"(c3)
                 : "r"(a0), "r"(a1), "r"(a2), "r"(a3), "r"(b0), "r"(b1));
}

// ---------------- x_proj: exact fp32 via packed f32x2 (half the FMA issues) ----------------
__global__ void __launch_bounds__(512) xp_kernel(const float* __restrict__ inp,
                                                 const float* __restrict__ w_ih) {
    const int b   = blockIdx.x;
    const int tc  = blockIdx.y;
    const int tid = threadIdx.x;  // 512 (j)
    __shared__ __align__(16) float s_in[32*64];
    const float* src = inp + (size_t)b*Tq*Iq + (size_t)tc*32*Iq;
    ((float4*)s_in)[tid] = ((const float4*)src)[tid];
    __syncthreads();

    u64 acc[32];
    #pragma unroll
    for (int tt = 0; tt < 32; tt++) acc[tt] = 0ull;

    #pragma unroll 4
    for (int ip = 0; ip < 32; ip++) {           // k-pair over i
        u64 wpk = packf2(w_ih[(2*ip)*Hq + tid], w_ih[(2*ip + 1)*Hq + tid]);
        #pragma unroll
        for (int tt = 0; tt < 32; tt++)
            acc[tt] = ffma2(*(const u64*)&s_in[tt*64 + 2*ip], wpk, acc[tt]);
    }
    #pragma unroll
    for (int tt = 0; tt < 32; tt++)
        g_xp[(size_t)(tc*32 + tt)*(Bq*Hq) + b*Hq + tid] = hsum2(acc[tt]);
}

// ---------------- RNN scan (quarter-range) — R12 structure, byte-for-byte ----------------
__global__ void __launch_bounds__(256, 1) __cluster_dims__(CLU, 1, 1)
rnn_kernel(const float* __restrict__ h_init, size_t h_stride, int t0, int tlen,
           const float* __restrict__ w_hh, float* __restrict__ outbuf) {
    __shared__ __align__(16) float  h_s[2][CLU][NB][64];
    __shared__ __align__(16) float  stage[2][NB*64];
    __shared__ __align__(16) float2 psum[NB][512];
    __shared__ __align__(8)  unsigned long long mbar_s[2][CLU];

    const int tid = threadIdx.x;
    uint32_t rank;
    asm("mov.u32 %0, %%cluster_ctarank;" : "=r"(rank));
    const int cid = blockIdx.x >> 3;
    const int j0  = (int)rank * 64;
    const int s   = tid >> 5;
    const int jl  = tid & 31;
    const int kb  = s * 64;

    u64 Wc0[32], Wc1[32];
    {
        const float* wbase = w_hh + (size_t)kb*Hq + j0 + jl*2;
        #pragma unroll
        for (int m = 0; m < 32; m++) {
            const float* wp = wbase + (size_t)(2*m)*Hq;
            Wc0[m] = packf2(wp[0], wp[Hq]);
            Wc1[m] = packf2(wp[1], wp[Hq + 1]);
        }
    }
    for (int e = tid; e < NB*Hq; e += 256) {
        int b = e >> 9, k = e & 511;
        h_s[0][k >> 6][b][k & 63] = h_init[(size_t)(cid*NB + b)*h_stride + k];
    }
    const uint32_t mbar0  = smem_u32(&mbar_s[0][0]);
    const uint32_t hbase  = smem_u32(&h_s[0][0][0][0]);
    const uint32_t sbase  = smem_u32(&stage[0][0]);
    if (tid == 0) {
        #pragma unroll
        for (int i = 0; i < 2*CLU; i++) mbar_init(mbar0 + 8u*i, 1);
    }
    __syncthreads();
    asm volatile("barrier.cluster.arrive.aligned;" ::: "memory");
    asm volatile("barrier.cluster.wait.aligned;"   ::: "memory");

    const int fb = tid >> 6;
    const int fc = tid & 63;
    uint32_t dst_p = 0, mb_p = 0;
    if (tid < CLU) {
        dst_p = mapa_u32(hbase + (uint32_t)rank * CHUNK_B, (uint32_t)tid);
        mb_p  = mapa_u32(mbar0 + 8u*rank, (uint32_t)tid);
    }
    const bool is_pusher = (tid < CLU) && (tid != (int)rank);
    const float* xp_col = g_xp + (size_t)(cid*NB + fb)*Hq + j0 + fc;

    float xpv = 0.f;
    if (tid < 128) xpv = __ldcg(xp_col + (size_t)t0*(Bq*Hq));

    for (int t = 0; t < tlen; t++) {
        const int g   = t0 + t;
        const int cur = t & 1, nxt = cur ^ 1;
        if (t < tlen - 1 && tid < CLU && tid != (int)rank)
            mbar_arrive_expect_tx(mbar0 + 8u*(nxt*CLU + tid), CHUNK_B);

        float xpn = 0.f;
        if (tid < 128 && t < tlen - 1)
            xpn = __ldcg(xp_col + (size_t)(g + 1)*(Bq*Hq));

        if (t > 0 && s != (int)rank) {
            const uint32_t par = (uint32_t)(((t >> 1) - ((t & 1) ^ 1)) & 1);
            mbar_wait_parity(mbar0 + 8u*(cur*CLU + s), par);
        }

        // ---- GEMV: 2 batches x 2 cols; LDS.128 feeds two k-pairs per load ----
        const float* hb0 = &h_s[cur][s][0][0];
        const float* hb1 = &h_s[cur][s][1][0];
        u64 a00 = 0ull, a01 = 0ull, a10 = 0ull, a11 = 0ull;
        #pragma unroll
        for (int m = 0; m < 16; m++) {
            ulonglong2 h0 = *(const ulonglong2*)&hb0[4*m];   // broadcast LDS.128
            ulonglong2 h1 = *(const ulonglong2*)&hb1[4*m];
            a00 = ffma2(h0.x, Wc0[2*m],     a00);
            a01 = ffma2(h0.x, Wc1[2*m],     a01);
            a10 = ffma2(h1.x, Wc0[2*m],     a10);
            a11 = ffma2(h1.x, Wc1[2*m],     a11);
            a00 = ffma2(h0.y, Wc0[2*m + 1], a00);
            a01 = ffma2(h0.y, Wc1[2*m + 1], a01);
            a10 = ffma2(h1.y, Wc0[2*m + 1], a10);
            a11 = ffma2(h1.y, Wc1[2*m + 1], a11);
        }
        {
            float2 p00 = unpackf2(a00), p01 = unpackf2(a01);
            float2 p10 = unpackf2(a10), p11 = unpackf2(a11);
            *(float4*)&psum[0][kb + jl*2] = make_float4(p00.x, p00.y, p01.x, p01.y);
            *(float4*)&psum[1][kb + jl*2] = make_float4(p10.x, p10.y, p11.x, p11.y);
        }
        __syncthreads();

        if (tid < 128) {
            float2 acc = psum[fb][fc];
            #pragma unroll
            for (int s2 = 1; s2 < 8; s2++) {
                float2 p = psum[fb][s2*64 + fc];
                acc.x += p.x; acc.y += p.y;
            }
            float v  = acc.x + acc.y + xpv;
            float hv = 1.f / (1.f + __expf(-v));
            const size_t bglob = (size_t)(cid*NB + fb);
            outbuf[RNN_OFF + bglob*Tq*Hq + (size_t)g*Hq + j0 + fc] = hv;
            if (g == Tq - 1) {
                outbuf[HN_OFF + bglob*Hq + j0 + fc] = hv;
            } else if (t < tlen - 1) {
                stage[nxt][fb*64 + fc] = hv;
                h_s[nxt][rank][fb][fc] = hv;
            }
        }
        xpv = xpn;
        __syncthreads();

        if (t < tlen - 1 && is_pusher) {
            fence_proxy_async_cta();
            bulk_copy_to_peer(dst_p + (uint32_t)(nxt * HSTRIDE),
                              sbase + (uint32_t)(nxt * CHUNK_B),
                              CHUNK_B,
                              mb_p + (uint32_t)(nxt * (CLU*8)));
        }
    }
}

// ---------------- fc1: tf32 mma.sync GEMM, QUARTER-aware (unchanged) ----------------
#define FM 128
#define FN 128
#define PAD 12
__global__ void __launch_bounds__(256, 1)
fc1_kernel(const float* __restrict__ A, const float* __restrict__ W,
           const float* __restrict__ bias, int qoff) {
    __shared__ __align__(16) uint32_t As[2][FM][PAD];
    __shared__ __align__(16) uint32_t Bs[2][FN][PAD];

    const int tid  = threadIdx.x;
    const int wid  = tid >> 5, lane = tid & 31;
    const int row0 = (blockIdx.y >> 1)*Tq + qoff + (blockIdx.y & 1)*FM;
    const int col0 = blockIdx.x * FN;
    const int wm   = wid >> 2;
    const int wn   = wid & 3;

    const int arow = tid >> 1, akq = (tid & 1) * 4;
    const int bk   = tid >> 5, bc  = (tid & 31) * 4;

    const uint32_t as0 = smem_u32(&As[0][0][0]);
    const uint32_t bs0 = smem_u32(&Bs[0][0][0]);
    const uint32_t a_off = ((uint32_t)((wm*64 + (lane & 15))*PAD + (lane >> 4)*4)) * 4u;
    const uint32_t b_off = ((uint32_t)((wn*32 + (lane & 7) + ((lane >> 4) & 1)*8)*PAD
                                       + ((lane >> 3) & 1)*4)) * 4u;
    const uint32_t BUFB = FM * PAD * 4u;

    float c[4][4][4];
    #pragma unroll
    for (int mt = 0; mt < 4; mt++)
        #pragma unroll
        for (int nt = 0; nt < 4; nt++)
            #pragma unroll
            for (int i = 0; i < 4; i++) c[mt][nt][i] = 0.f;

    uint4 ar; uint4 br;
    {
        float4 a4 = *(const float4*)&A[(size_t)(row0 + arow)*Hq + akq];
        float4 b4 = *(const float4*)&W[(size_t)bk*Hq + col0 + bc];
        ar = make_uint4(cvt_tf32(a4.x), cvt_tf32(a4.y), cvt_tf32(a4.z), cvt_tf32(a4.w));
        br = make_uint4(cvt_tf32(b4.x), cvt_tf32(b4.y), cvt_tf32(b4.z), cvt_tf32(b4.w));
    }

    for (int ks = 0; ks < 64; ks++) {
        const int buf = ks & 1;
        *(uint4*)&As[buf][arow][akq] = ar;
        Bs[buf][bc + 0][bk] = br.x;
        Bs[buf][bc + 1][bk] = br.y;
        Bs[buf][bc + 2][bk] = br.z;
        Bs[buf][bc + 3][bk] = br.w;
        if (ks < 63) {
            const int kt = (ks + 1) * 8;
            float4 a4 = *(const float4*)&A[(size_t)(row0 + arow)*Hq + kt + akq];
            float4 b4 = *(const float4*)&W[(size_t)(kt + bk)*Hq + col0 + bc];
            ar = make_uint4(cvt_tf32(a4.x), cvt_tf32(a4.y), cvt_tf32(a4.z), cvt_tf32(a4.w));
            br = make_uint4(cvt_tf32(b4.x), cvt_tf32(b4.y), cvt_tf32(b4.z), cvt_tf32(b4.w));
        }
        __syncthreads();

        uint32_t af[4][4], bf[4][2];
        #pragma unroll
        for (int mt = 0; mt < 4; mt++)
            ldsm_x4(af[mt][0], af[mt][1], af[mt][2], af[mt][3],
                    as0 + buf*BUFB + a_off + (uint32_t)(mt*16*PAD*4));
        #pragma unroll
        for (int np = 0; np < 2; np++)
            ldsm_x4(bf[2*np][0], bf[2*np][1], bf[2*np + 1][0], bf[2*np + 1][1],
                    bs0 + buf*BUFB + b_off + (uint32_t)(np*16*PAD*4));

        #pragma unroll
        for (int mt = 0; mt < 4; mt++)
            #pragma unroll
            for (int nt = 0; nt < 4; nt++)
                mma_tf32(c[mt][nt][0], c[mt][nt][1], c[mt][nt][2], c[mt][nt][3],
                         af[mt][0], af[mt][1], af[mt][2], af[mt][3],
                         bf[nt][0], bf[nt][1]);
    }

    const int gq = lane >> 2, tq = lane & 3;
    #pragma unroll
    for (int nt = 0; nt < 4; nt++) {
        const int cb = col0 + wn*32 + nt*8 + 2*tq;
        const float2 bv = *(const float2*)&bias[cb];
        #pragma unroll
        for (int mt = 0; mt < 4; mt++) {
            const int r0 = row0 + wm*64 + mt*16 + gq;
            float2 o0, o1;
            o0.x = fmaxf(c[mt][nt][0] + bv.x, 0.f);
            o0.y = fmaxf(c[mt][nt][1] + bv.y, 0.f);
            o1.x = fmaxf(c[mt][nt][2] + bv.x, 0.f);
            o1.y = fmaxf(c[mt][nt][3] + bv.y, 0.f);
            *(float2*)&g_hidden[(size_t)r0*Hq + cb]       = o0;
            *(float2*)&g_hidden[(size_t)(r0 + 8)*Hq + cb] = o1;
        }
    }
}

// ---------------- fc2 (quarter-aware, unchanged) ----------------
__global__ void fc2_kernel(const float* __restrict__ w2,
                           const float* __restrict__ b2,
                           float* __restrict__ out, int qoff) {
    __shared__ float w2s[Hq*Aq];
    const int tid = threadIdx.x;   // 256
    for (int e = tid; e < Hq*Aq; e += 256) w2s[e] = w2[e];
    __syncthreads();

    const int r = tid >> 4;
    const int a = tid & 15;
    const size_t row = (size_t)(blockIdx.x >> 4)*Tq + qoff + (blockIdx.x & 15)*16 + r;
    const float* hrow = &g_hidden[row*Hq];

    float acc = 0.f;
    #pragma unroll 8
    for (int k = 0; k < Hq; k += 4) {
        float4 hv = *(const float4*)&hrow[k];
        acc = fmaf(hv.x, w2s[(k+0)*Aq + a], acc);
        acc = fmaf(hv.y, w2s[(k+1)*Aq + a], acc);
        acc = fmaf(hv.z, w2s[(k+2)*Aq + a], acc);
        acc = fmaf(hv.w, w2s[(k+3)*Aq + a], acc);
    }
    float v = acc + b2[a];
    out[row*Aq + a] = 1.f / (1.f + __expf(-v));
}

extern "C" void kernel_launch(void* const* d_in, const int* in_sizes, int n_in,
                              void* d_out, int out_size) {
    const float* inp  = (const float*)d_in[0];
    const float* hn   = (const float*)d_in[1];
    const float* w_hh = (const float*)d_in[2];
    const float* w_ih = (const float*)d_in[3];
    const float* fc1w = (const float*)d_in[4];
    const float* fc1b = (const float*)d_in[5];
    const float* fc2w = (const float*)d_in[6];
    const float* fc2b = (const float*)d_in[7];
    float* out = (float*)d_out;

    // serial xp (fast u64 version) -> rnn quarters; fc(q) forked onto s2 under rnn(q+1)
    xp_kernel<<<dim3(32, 32), 512>>>(inp, w_ih);

    rnn_kernel<<<NCL*CLU, 256>>>(hn, (size_t)Hq, 0, QT, w_hh, out);
    cudaEventRecord(g_ov.eq[0], 0);
    rnn_kernel<<<NCL*CLU, 256>>>(out + RNN_OFF + (size_t)(QT - 1)*Hq, (size_t)Tq*Hq, QT, QT, w_hh, out);
    cudaEventRecord(g_ov.eq[1], 0);
    rnn_kernel<<<NCL*CLU, 256>>>(out + RNN_OFF + (size_t)(2*QT - 1)*Hq, (size_t)Tq*Hq, 2*QT, QT, w_hh, out);
    cudaEventRecord(g_ov.eq[2], 0);
    rnn_kernel<<<NCL*CLU, 256>>>(out + RNN_OFF + (size_t)(3*QT - 1)*Hq, (size_t)Tq*Hq, 3*QT, QT, w_hh, out);

    for (int q = 0; q < 3; q++) {
        cudaStreamWaitEvent(g_ov.s2, g_ov.eq[q], 0);
        fc1_kernel<<<dim3(4, 64), 256, 0, g_ov.s2>>>(out + RNN_OFF, fc1w, fc1b, q*QT);
        fc2_kernel<<<512, 256, 0, g_ov.s2>>>(fc2w, fc2b, out, q*QT);
    }
    cudaEventRecord(g_ov.ej, g_ov.s2);

    fc1_kernel<<<dim3(4, 64), 256>>>(out + RNN_OFF, fc1w, fc1b, 3*QT);
    cudaStreamWaitEvent(0, g_ov.ej, 0);
    fc2_kernel<<<512, 256>>>(fc2w, fc2b, out, 3*QT);
}